// round 1
// baseline (speedup 1.0000x reference)
#include <cuda_runtime.h>
#include <cstddef>

// Problem constants
#define NB 1024          // 32*32 nodes per time slice
#define NT 9
#define TN (NT * NB)     // 9216

// Scratch: A_t stencil coefficients for t = 0..7 (operator at time slice t+1).
// Layout [t][node][9], offset index j = (dy+1)*3 + (dx+1). Invalid moves = 0.
__device__ float g_A[8 * NB * 9];

// ---------------------------------------------------------------------------
// Kernel 1: per-node 9-point stencil coefficients of A (Dirichlet validity
// baked in as zeros).  DX = DY = DT = 1.
// ---------------------------------------------------------------------------
__global__ void coef_kernel(const float* __restrict__ kappa,
                            const float* __restrict__ m,
                            const float* __restrict__ H) {
    int tid = blockIdx.x * blockDim.x + threadIdx.x;
    if (tid >= 8 * NB) return;
    int t = tid >> 10;          // 0..7
    int n = tid & (NB - 1);     // node
    int ts = t + 1;             // A[t] uses time slice t+1 (m_b[:,:,1:] etc.)

    // strides: kappa [1,1,NB,NT]; m [1,2,NB,NT]; H [1,2,2,NB,NT]
    float kap = kappa[n * NT + ts];
    float k2  = kap * kap;
    float m1  = m[(0 * NB + n) * NT + ts];
    float m2  = m[(1 * NB + n) * NT + ts];
    float H11 = H[(0 * NB + n) * NT + ts];          // (0,0)
    float H12 = H[(1 * NB + n) * NT + ts];          // (0,1)
    float H22 = H[(3 * NB + n) * NT + ts];          // (1,1)

    int ix = n & 31, iy = n >> 5;
    bool xm = ix > 0, xp = ix < 31, ym = iy > 0, yp = iy < 31;

    float c[9];
    c[4] = k2 + 2.0f * H11 + 2.0f * H22;                 // center
    c[5] = xp          ? ( 0.5f * m1 - H11) : 0.0f;      // (+x)
    c[3] = xm          ? (-0.5f * m1 - H11) : 0.0f;      // (-x)
    c[7] = yp          ? ( 0.5f * m2 - H22) : 0.0f;      // (+y)
    c[1] = ym          ? (-0.5f * m2 - H22) : 0.0f;      // (-y)
    c[8] = (xp && yp)  ? (-0.5f * H12)      : 0.0f;      // (+x,+y)
    c[2] = (xp && ym)  ? ( 0.5f * H12)      : 0.0f;      // (+x,-y)
    c[6] = (xm && yp)  ? ( 0.5f * H12)      : 0.0f;      // (-x,+y)
    c[0] = (xm && ym)  ? (-0.5f * H12)      : 0.0f;      // (-x,-y)

#pragma unroll
    for (int j = 0; j < 9; j++) g_A[(t * NB + n) * 9 + j] = c[j];
}

// ---------------------------------------------------------------------------
// Kernel 2: off-diagonal blocks.  Q_sym[t, t+1] = Q_sym[t+1, t]
//         = -0.5 * (invM_t + invM_t^T),  invM = I + A.
// One thread per (t, p, stencil offset j).
// ---------------------------------------------------------------------------
__global__ void offdiag_kernel(float* __restrict__ out) {
    int tid = blockIdx.x * blockDim.x + threadIdx.x;
    if (tid >= 8 * NB * 9) return;
    int t   = tid / (NB * 9);
    int rem = tid - t * NB * 9;
    int p   = rem / 9;
    int j   = rem - p * 9;
    int dy  = j / 3 - 1, dx = j - (j / 3) * 3 - 1;
    int q   = p + dy * 32 + dx;
    if (q < 0 || q >= NB) return;

    float add = (j == 4) ? 1.0f : 0.0f;                     // invM = A + I
    float a = g_A[(t * NB + p) * 9 + j] + add;              // invM[p][q]
    float b = g_A[(t * NB + q) * 9 + (8 - j)] + add;        // invM[q][p]
    float v = -0.5f * (a + b);

    out[(size_t)(t * NB + p) * TN + (size_t)(t + 1) * NB + q] = v;  // (t, t+1)
    out[(size_t)((t + 1) * NB + p) * TN + (size_t)t * NB + q] = v;  // (t+1, t)
}

// ---------------------------------------------------------------------------
// Kernel 3: diagonal blocks.
//   i = 0:      A0^T A0 + 1.05 I  (already symmetric)
//   i = 1..7:   0.5*(MM + MM^T) + 1.05 I,   MM = invM_{i-1}^2
//   i = 8:      0.5*(MM + MM^T) + 0.05 I,   MM = invM_7^2
// Entries live in a 5x5 linear-offset neighborhood.  One CTA per
// (block i, 64-row chunk); coefficient table for the block's timestep in SMEM.
// ---------------------------------------------------------------------------
__global__ void diag_kernel(float* __restrict__ out) {
    const int CHUNK = 64;                    // rows per CTA
    int i     = blockIdx.x >> 4;             // 0..8 diag block
    int chunk = blockIdx.x & 15;             // 0..15
    int t     = (i == 0) ? 0 : (i - 1);

    __shared__ float sA[NB * 9];             // 36 KB
    for (int k = threadIdx.x; k < NB * 9; k += blockDim.x)
        sA[k] = g_A[t * NB * 9 + k];
    __syncthreads();

    for (int e = threadIdx.x; e < CHUNK * 25; e += blockDim.x) {
        int p  = chunk * CHUNK + e / 25;
        int o  = e - (e / 25) * 25;
        int ey = o / 5 - 2, ex = o - (o / 5) * 5 - 2;
        int q  = p + ey * 32 + ex;
        if (q < 0 || q >= NB) continue;

        float v;
        if (i == 0) {
            // (A^T A)[p][q] = sum_r A[r][p] * A[r][q]
            float acc = 0.0f;
#pragma unroll
            for (int j = 0; j < 9; j++) {
                int dy = j / 3 - 1, dx = j - (j / 3) * 3 - 1;
                int r = p + dy * 32 + dx;
                if (r < 0 || r >= NB) continue;
                int ddy = ey - dy, ddx = ex - dx;
                if (ddy < -1 || ddy > 1 || ddx < -1 || ddx > 1) continue;
                int j2 = (ddy + 1) * 3 + (ddx + 1);
                acc += sA[r * 9 + (8 - j)] * sA[r * 9 + j2];
            }
            v = acc + ((q == p) ? 1.05f : 0.0f);
        } else {
            float mmpq = 0.0f, mmqp = 0.0f;
#pragma unroll
            for (int j = 0; j < 9; j++) {
                int dy = j / 3 - 1, dx = j - (j / 3) * 3 - 1;
                // MM[p][q] term: p -> r -> q
                {
                    int r = p + dy * 32 + dx;
                    int ddy = ey - dy, ddx = ex - dx;
                    if (r >= 0 && r < NB &&
                        ddy >= -1 && ddy <= 1 && ddx >= -1 && ddx <= 1) {
                        int j2 = (ddy + 1) * 3 + (ddx + 1);
                        float a = sA[p * 9 + j]  + ((j  == 4) ? 1.0f : 0.0f);
                        float b = sA[r * 9 + j2] + ((j2 == 4) ? 1.0f : 0.0f);
                        mmpq += a * b;
                    }
                }
                // MM[q][p] term: q -> s -> p
                {
                    int s = q + dy * 32 + dx;
                    int ddy = -ey - dy, ddx = -ex - dx;
                    if (s >= 0 && s < NB &&
                        ddy >= -1 && ddy <= 1 && ddx >= -1 && ddx <= 1) {
                        int j2 = (ddy + 1) * 3 + (ddx + 1);
                        float a = sA[q * 9 + j]  + ((j  == 4) ? 1.0f : 0.0f);
                        float b = sA[s * 9 + j2] + ((j2 == 4) ? 1.0f : 0.0f);
                        mmqp += a * b;
                    }
                }
            }
            v = 0.5f * (mmpq + mmqp) +
                ((q == p) ? ((i < 8) ? 1.05f : 0.05f) : 0.0f);
        }
        out[(size_t)(i * NB + p) * TN + (size_t)i * NB + q] = v;
    }
}

// ---------------------------------------------------------------------------
// Launcher.  Inputs (metadata order): kappa, m, H, tau (tau unused).
// Output: float32 [1, 9216, 9216].
// ---------------------------------------------------------------------------
extern "C" void kernel_launch(void* const* d_in, const int* in_sizes, int n_in,
                              void* d_out, int out_size) {
    const float* kappa = (const float*)d_in[0];
    const float* m     = (const float*)d_in[1];
    const float* H     = (const float*)d_in[2];
    float* out = (float*)d_out;

    // 1) zero-fill the full 340 MB output (dominates runtime; HBM-bound)
    cudaMemsetAsync(d_out, 0, (size_t)out_size * sizeof(float), 0);

    // 2) stencil coefficients (8 timesteps x 1024 nodes)
    coef_kernel<<<(8 * NB + 255) / 256, 256>>>(kappa, m, H);

    // 3) off-diagonal blocks (16 blocks, banded)
    offdiag_kernel<<<(8 * NB * 9 + 255) / 256, 256>>>(out);

    // 4) diagonal blocks (9 blocks, 5x5-banded)
    diag_kernel<<<9 * 16, 256>>>(out);
}

// round 2
// speedup vs baseline: 1.0938x; 1.0938x over previous
#include <cuda_runtime.h>
#include <cstddef>

#define NB 1024          // 32*32 nodes per time slice
#define NT 9
#define TN (NT * NB)     // 9216

// Stencil coefficients of A_t for t = 0..7 (operator at time slice t+1).
// Layout [t][node][9], j = (dy+1)*3 + (dx+1). Invalid (boundary) moves = 0.
__device__ float g_A[8 * NB * 9];

// ---------------------------------------------------------------------------
// Kernel 1: per-node 9-point stencil coefficients (Dirichlet zeros baked in).
// ---------------------------------------------------------------------------
__global__ void coef_kernel(const float* __restrict__ kappa,
                            const float* __restrict__ m,
                            const float* __restrict__ H) {
    int tid = blockIdx.x * blockDim.x + threadIdx.x;
    if (tid >= 8 * NB) return;
    int t = tid >> 10;
    int n = tid & (NB - 1);
    int ts = t + 1;

    float kap = kappa[n * NT + ts];
    float k2  = kap * kap;
    float m1  = m[(0 * NB + n) * NT + ts];
    float m2  = m[(1 * NB + n) * NT + ts];
    float H11 = H[(0 * NB + n) * NT + ts];
    float H12 = H[(1 * NB + n) * NT + ts];
    float H22 = H[(3 * NB + n) * NT + ts];

    int ix = n & 31, iy = n >> 5;
    bool xm = ix > 0, xp = ix < 31, ym = iy > 0, yp = iy < 31;

    float c[9];
    c[4] = k2 + 2.0f * H11 + 2.0f * H22;
    c[5] = xp         ? ( 0.5f * m1 - H11) : 0.0f;
    c[3] = xm         ? (-0.5f * m1 - H11) : 0.0f;
    c[7] = yp         ? ( 0.5f * m2 - H22) : 0.0f;
    c[1] = ym         ? (-0.5f * m2 - H22) : 0.0f;
    c[8] = (xp && yp) ? (-0.5f * H12)      : 0.0f;
    c[2] = (xp && ym) ? ( 0.5f * H12)      : 0.0f;
    c[6] = (xm && yp) ? ( 0.5f * H12)      : 0.0f;
    c[0] = (xm && ym) ? (-0.5f * H12)      : 0.0f;

#pragma unroll
    for (int j = 0; j < 9; j++) g_A[(t * NB + n) * 9 + j] = c[j];
}

// ---------------------------------------------------------------------------
// Band-value helpers (boundary wraps give exact 0 via stored zero coefs).
// ---------------------------------------------------------------------------
__device__ __forceinline__ float offdiag_val(int t, int p, int q) {
    // -0.5*(invM[p][q] + invM[q][p]),  invM = I + A_t
    int d = q - p + 33;
    if ((unsigned)d > 66u || (d & 31) > 2) return 0.0f;
    int j = (d >> 5) * 3 + (d & 31);
    float add = (j == 4) ? 1.0f : 0.0f;
    float a = g_A[(t * NB + p) * 9 + j] + add;
    float b = g_A[(t * NB + q) * 9 + (8 - j)] + add;
    return -0.5f * (a + b);
}

__device__ __forceinline__ float diag_val(int i, int p, int q) {
    int delta = q - p;
    // decompose delta = ey*32 + ex with |ex|<=2 (unique); out-of-pattern
    // deltas yield ex with |ex|>2 -> all paths reject -> 0.
    int ey = ((delta + 66) + 2) / 32 - 2;
    int ex = delta - ey * 32;
    float v;
    if (i == 0) {
        const float* sA = g_A;                 // t = 0
        float acc = 0.0f;
#pragma unroll
        for (int j = 0; j < 9; j++) {
            int dy = j / 3 - 1, dx = j - (j / 3) * 3 - 1;
            int r = p + dy * 32 + dx;
            if (r < 0 || r >= NB) continue;
            int ddy = ey - dy, ddx = ex - dx;
            if (ddy < -1 || ddy > 1 || ddx < -1 || ddx > 1) continue;
            int j2 = (ddy + 1) * 3 + (ddx + 1);
            acc += sA[r * 9 + (8 - j)] * sA[r * 9 + j2];
        }
        v = acc + ((q == p) ? 1.05f : 0.0f);
    } else {
        const float* sA = g_A + (size_t)(i - 1) * NB * 9;
        float mmpq = 0.0f, mmqp = 0.0f;
#pragma unroll
        for (int j = 0; j < 9; j++) {
            int dy = j / 3 - 1, dx = j - (j / 3) * 3 - 1;
            {   // MM[p][q]: p -> r -> q
                int r = p + dy * 32 + dx;
                int ddy = ey - dy, ddx = ex - dx;
                if (r >= 0 && r < NB &&
                    ddy >= -1 && ddy <= 1 && ddx >= -1 && ddx <= 1) {
                    int j2 = (ddy + 1) * 3 + (ddx + 1);
                    float a = sA[p * 9 + j]  + ((j  == 4) ? 1.0f : 0.0f);
                    float b = sA[r * 9 + j2] + ((j2 == 4) ? 1.0f : 0.0f);
                    mmpq += a * b;
                }
            }
            {   // MM[q][p]: q -> s -> p
                int s = q + dy * 32 + dx;
                int ddy = -ey - dy, ddx = -ex - dx;
                if (s >= 0 && s < NB &&
                    ddy >= -1 && ddy <= 1 && ddx >= -1 && ddx <= 1) {
                    int j2 = (ddy + 1) * 3 + (ddx + 1);
                    float a = sA[q * 9 + j]  + ((j  == 4) ? 1.0f : 0.0f);
                    float b = sA[s * 9 + j2] + ((j2 == 4) ? 1.0f : 0.0f);
                    mmqp += a * b;
                }
            }
        }
        v = 0.5f * (mmpq + mmqp) +
            ((q == p) ? ((i < 8) ? 1.05f : 0.05f) : 0.0f);
    }
    return v;
}

// ---------------------------------------------------------------------------
// Kernel 2: single-pass fill. One CTA per output row; each thread streams
// 9 float4s (2304 float4 = 9216 floats per row). Zeros off-band, computed
// values in-band. Every byte of out is written exactly once.
// ---------------------------------------------------------------------------
__global__ __launch_bounds__(256) void fill_kernel(float* __restrict__ out) {
    int r = blockIdx.x;                 // output row 0..9215
    int i = r >> 10;                    // block row
    int p = r & (NB - 1);               // row within block
    float4* rowp = (float4*)(out + (size_t)r * TN);

#pragma unroll
    for (int it = 0; it < 9; it++) {
        int c4 = threadIdx.x + it * 256;    // float4 column index 0..2303
        int jb = c4 >> 8;                   // column block (256 float4/block)
        int q0 = (c4 << 2) & (NB - 1);      // first col within block
        float4 v = make_float4(0.f, 0.f, 0.f, 0.f);

        if (jb == i) {
            if (q0 + 3 >= p - 66 && q0 <= p + 66) {
                v.x = diag_val(i, p, q0);
                v.y = diag_val(i, p, q0 + 1);
                v.z = diag_val(i, p, q0 + 2);
                v.w = diag_val(i, p, q0 + 3);
            }
        } else if (jb == i - 1 || jb == i + 1) {
            int t = (jb < i) ? jb : i;      // min(i, jb)
            if (q0 + 3 >= p - 33 && q0 <= p + 33) {
                v.x = offdiag_val(t, p, q0);
                v.y = offdiag_val(t, p, q0 + 1);
                v.z = offdiag_val(t, p, q0 + 2);
                v.w = offdiag_val(t, p, q0 + 3);
            }
        }
        __stcs(&rowp[c4], v);               // streaming store, bypass L2 keep
    }
}

// ---------------------------------------------------------------------------
// Launcher. Inputs: kappa, m, H, tau (unused). Output: fp32 [1, 9216, 9216].
// ---------------------------------------------------------------------------
extern "C" void kernel_launch(void* const* d_in, const int* in_sizes, int n_in,
                              void* d_out, int out_size) {
    const float* kappa = (const float*)d_in[0];
    const float* m     = (const float*)d_in[1];
    const float* H     = (const float*)d_in[2];
    float* out = (float*)d_out;

    coef_kernel<<<(8 * NB + 255) / 256, 256>>>(kappa, m, H);
    fill_kernel<<<TN, 256>>>(out);
}